// round 8
// baseline (speedup 1.0000x reference)
#include <cuda_runtime.h>
#include <cstring>

#define Bn 512
#define Tn 512
#define Nn 64
#define NT 32   // single warp per block; one warp drives TWO batches

typedef unsigned long long ull;

__device__ __forceinline__ ull fma2(ull a, ull b, ull c) {
    ull d;
    asm("fma.rn.f32x2 %0, %1, %2, %3;" : "=l"(d) : "l"(a), "l"(b), "l"(c));
    return d;
}

__device__ __forceinline__ ull add2(ull a, ull b) {
    ull d;
    asm("add.rn.f32x2 %0, %1, %2;" : "=l"(d) : "l"(a), "l"(b));
    return d;
}

__device__ __forceinline__ ull pack2(float x, float y) {
    float2 f; f.x = x; f.y = y;
    ull u;
    memcpy(&u, &f, 8);
    return u;
}

__global__ void __launch_bounds__(NT) crf_kernel(
    const float* __restrict__ inp,    // [B,T,N]
    const float* __restrict__ trans,  // [N,N]
    const int*   __restrict__ tags,   // [B,T]
    const int*   __restrict__ lens,   // [B]
    float*       __restrict__ out)    // [512 + 4096]
{
    const int bA = 2 * blockIdx.x;
    const int bB = bA + 1;
    const int l  = threadIdx.x;

    // fused transition_params copy: 16 elements per block (256*16 = 4096)
    if (l < 16) {
        int idx = blockIdx.x * 16 + l;
        out[Bn + idx] = trans[idx];
    }

    const int cA = 2 * l;
    const int cB = 2 * l + 1;

    __shared__ float pbA[2][Nn];
    __shared__ float pbB[2][Nn];

    const int LA = lens[bA];
    const int LB = lens[bB];
    const int lastA = (LA - 1) > 0 ? (LA - 1) : 0;
    const int lastB = (LB - 1) > 0 ? (LB - 1) : 0;
    const int maxlast = lastA > lastB ? lastA : lastB;

    const long baseA = (long)bA * Tn;
    const long baseB = (long)bB * Tn;
    const float* __restrict__ erowA = inp + baseA * Nn;
    const float* __restrict__ erowB = inp + baseB * Nn;

    // ---------------- sequence scores (parallel over t, warp reduce) ---------
    float sA = 0.f, sB = 0.f;
    for (int t = l; t < Tn; t += NT) {
        if (t < LA) {
            int tg = tags[baseA + t];
            sA += erowA[t * Nn + tg];
            if (t >= 1) sA += trans[tags[baseA + t - 1] * Nn + tg];
        }
        if (t < LB) {
            int tg = tags[baseB + t];
            sB += erowB[t * Nn + tg];
            if (t >= 1) sB += trans[tags[baseB + t - 1] * Nn + tg];
        }
    }
    #pragma unroll
    for (int o = 16; o > 0; o >>= 1) {
        sA += __shfl_down_sync(0xffffffffu, sA, o);
        sB += __shfl_down_sync(0xffffffffu, sB, o);
    }
    const float seqA = sA, seqB = sB;   // valid in lane 0

    // ---------------- E columns for cA, cB (SHARED by both batches) ----------
    ull EA[32], EB[32];
    #pragma unroll
    for (int i = 0; i < 32; i++) {
        float a0 = __expf(trans[(2 * i)     * Nn + cA]);
        float a1 = __expf(trans[(2 * i + 1) * Nn + cA]);
        float b0 = __expf(trans[(2 * i)     * Nn + cB]);
        float b1 = __expf(trans[(2 * i + 1) * Nn + cB]);
        EA[i] = pack2(a0, a1);
        EB[i] = pack2(b0, b1);
    }

    // ---------------- init both recurrences ----------------
    float qA0 = __expf(erowA[cA]);
    float qA1 = __expf(erowA[cB]);
    float qB0 = __expf(erowB[cA]);
    float qB1 = __expf(erowB[cB]);
    *reinterpret_cast<float2*>(&pbA[0][cA]) = make_float2(qA0, qA1);
    *reinterpret_cast<float2*>(&pbB[0][cA]) = make_float2(qB0, qB1);
    int KA = 0, KB = 0;
    // captured finals (valid when last == 0 immediately)
    float fA0 = qA0, fA1 = qA1, fB0 = qB0, fB1 = qB1;
    int KfA = 0, KfB = 0;
    int buf = 0;

    // one interleaved double-step at time TCUR; X* = exp(emissions)
#define DSTEP(TCUR, XA0, XA1, XB0, XB1)                                      \
    do {                                                                     \
        __syncwarp();                                                        \
        const float4* p4a = reinterpret_cast<const float4*>(pbA[buf]);       \
        const float4* p4b = reinterpret_cast<const float4*>(pbB[buf]);       \
        float4 vA = p4a[0];                                                  \
        float4 vB = p4b[0];                                                  \
        int ebA = (__float_as_int(vA.x) >> 23) & 0xFF;                       \
        int ebB = (__float_as_int(vB.x) >> 23) & 0xFF;                       \
        ebA = ebA < 64 ? 64 : (ebA > 190 ? 190 : ebA);                       \
        ebB = ebB < 64 ? 64 : (ebB > 190 ? 190 : ebB);                       \
        const float scA = __int_as_float((254 - ebA) << 23);                 \
        const float scB = __int_as_float((254 - ebB) << 23);                 \
        KA += ebA - 127;                                                     \
        KB += ebB - 127;                                                     \
        ull aA0, aA1, aB0, aB1, bA0, bA1, bB0, bB1;                          \
        {                                                                    \
            ull paLo = pack2(vA.x, vA.y), paHi = pack2(vA.z, vA.w);          \
            ull pbLo = pack2(vB.x, vB.y), pbHi = pack2(vB.z, vB.w);          \
            aA0 = fma2(paLo, EA[0], 0ull); aA1 = fma2(paHi, EA[1], 0ull);    \
            aB0 = fma2(paLo, EB[0], 0ull); aB1 = fma2(paHi, EB[1], 0ull);    \
            bA0 = fma2(pbLo, EA[0], 0ull); bA1 = fma2(pbHi, EA[1], 0ull);    \
            bB0 = fma2(pbLo, EB[0], 0ull); bB1 = fma2(pbHi, EB[1], 0ull);    \
        }                                                                    \
        _Pragma("unroll")                                                    \
        for (int m = 1; m < 16; m++) {                                       \
            float4 wA = p4a[m];                                              \
            float4 wB = p4b[m];                                              \
            ull paLo = pack2(wA.x, wA.y), paHi = pack2(wA.z, wA.w);          \
            ull pbLo = pack2(wB.x, wB.y), pbHi = pack2(wB.z, wB.w);          \
            aA0 = fma2(paLo, EA[2 * m],     aA0);                            \
            aA1 = fma2(paHi, EA[2 * m + 1], aA1);                            \
            aB0 = fma2(paLo, EB[2 * m],     aB0);                            \
            aB1 = fma2(paHi, EB[2 * m + 1], aB1);                            \
            bA0 = fma2(pbLo, EA[2 * m],     bA0);                            \
            bA1 = fma2(pbHi, EA[2 * m + 1], bA1);                            \
            bB0 = fma2(pbLo, EB[2 * m],     bB0);                            \
            bB1 = fma2(pbHi, EB[2 * m + 1], bB1);                            \
        }                                                                    \
        ull sAA = add2(aA0, aA1), sAB = add2(aB0, aB1);                      \
        ull sBA = add2(bA0, bA1), sBB = add2(bB0, bB1);                      \
        float2 gAA, gAB, gBA, gBB;                                           \
        memcpy(&gAA, &sAA, 8); memcpy(&gAB, &sAB, 8);                        \
        memcpy(&gBA, &sBA, 8); memcpy(&gBB, &sBB, 8);                        \
        qA0 = (XA0) * (gAA.x + gAA.y) * scA;                                 \
        qA1 = (XA1) * (gAB.x + gAB.y) * scA;                                 \
        qB0 = (XB0) * (gBA.x + gBA.y) * scB;                                 \
        qB1 = (XB1) * (gBB.x + gBB.y) * scB;                                 \
        const bool capA = ((TCUR) == lastA);                                 \
        const bool capB = ((TCUR) == lastB);                                 \
        fA0 = capA ? qA0 : fA0;  fA1 = capA ? qA1 : fA1;                     \
        KfA = capA ? KA  : KfA;                                              \
        fB0 = capB ? qB0 : fB0;  fB1 = capB ? qB1 : fB1;                     \
        KfB = capB ? KB  : KfB;                                              \
        *reinterpret_cast<float2*>(&pbA[buf ^ 1][cA]) = make_float2(qA0, qA1);\
        *reinterpret_cast<float2*>(&pbB[buf ^ 1][cA]) = make_float2(qB0, qB1);\
        buf ^= 1;                                                            \
    } while (0)

#define EMA(ROW) (*reinterpret_cast<const float2*>(                          \
        erowA + ((((ROW) < Tn - 1) ? (ROW) : (Tn - 1)) * Nn) + cA))
#define EMB(ROW) (*reinterpret_cast<const float2*>(                          \
        erowB + ((((ROW) < Tn - 1) ? (ROW) : (Tn - 1)) * Nn) + cA))

    float2 a0 = EMA(1), a1 = EMA(2), a2 = EMA(3), a3 = EMA(4);
    float2 b0 = EMB(1), b1 = EMB(2), b2 = EMB(3), b3 = EMB(4);

    int t = 1;
    for (; t + 3 <= maxlast; t += 4) {
        float2 na0 = EMA(t + 4), na1 = EMA(t + 5), na2 = EMA(t + 6), na3 = EMA(t + 7);
        float2 nb0 = EMB(t + 4), nb1 = EMB(t + 5), nb2 = EMB(t + 6), nb3 = EMB(t + 7);
        float xa00 = __expf(a0.x), xa01 = __expf(a0.y);
        float xa10 = __expf(a1.x), xa11 = __expf(a1.y);
        float xa20 = __expf(a2.x), xa21 = __expf(a2.y);
        float xa30 = __expf(a3.x), xa31 = __expf(a3.y);
        float xb00 = __expf(b0.x), xb01 = __expf(b0.y);
        float xb10 = __expf(b1.x), xb11 = __expf(b1.y);
        float xb20 = __expf(b2.x), xb21 = __expf(b2.y);
        float xb30 = __expf(b3.x), xb31 = __expf(b3.y);
        DSTEP(t,     xa00, xa01, xb00, xb01);
        DSTEP(t + 1, xa10, xa11, xb10, xb11);
        DSTEP(t + 2, xa20, xa21, xb20, xb21);
        DSTEP(t + 3, xa30, xa31, xb30, xb31);
        a0 = na0; a1 = na1; a2 = na2; a3 = na3;
        b0 = nb0; b1 = nb1; b2 = nb2; b3 = nb3;
    }
    if (t <= maxlast) {
        float xa0v = __expf(a0.x), xa1v = __expf(a0.y);
        float xb0v = __expf(b0.x), xb1v = __expf(b0.y);
        DSTEP(t, xa0v, xa1v, xb0v, xb1v); t++;
    }
    if (t <= maxlast) {
        float xa0v = __expf(a1.x), xa1v = __expf(a1.y);
        float xb0v = __expf(b1.x), xb1v = __expf(b1.y);
        DSTEP(t, xa0v, xa1v, xb0v, xb1v); t++;
    }
    if (t <= maxlast) {
        float xa0v = __expf(a2.x), xa1v = __expf(a2.y);
        float xb0v = __expf(b2.x), xb1v = __expf(b2.y);
        DSTEP(t, xa0v, xa1v, xb0v, xb1v); t++;
    }

#undef DSTEP
#undef EMA
#undef EMB

    // ---------------- final log-normalizers (warp reduces) ----------------
    float uA = fA0 + fA1;
    float uB = fB0 + fB1;
    #pragma unroll
    for (int o = 16; o > 0; o >>= 1) {
        uA += __shfl_down_sync(0xffffffffu, uA, o);
        uB += __shfl_down_sync(0xffffffffu, uB, o);
    }

    if (l == 0) {
        const float LN2_HI = 0.693145751953125f;
        const float LN2_LO = 1.428606765330187e-06f;
        float KfAf = (float)KfA;
        float KfBf = (float)KfB;
        float lnA = fmaf(KfAf, LN2_LO, fmaf(KfAf, LN2_HI, __logf(uA)));
        float lnB = fmaf(KfBf, LN2_LO, fmaf(KfBf, LN2_HI, __logf(uB)));
        out[bA] = seqA - lnA;
        out[bB] = seqB - lnB;
    }
}

extern "C" void kernel_launch(void* const* d_in, const int* in_sizes, int n_in,
                              void* d_out, int out_size) {
    const float* inp   = (const float*)d_in[0];
    const float* trans = (const float*)d_in[1];
    const int*   tags  = (const int*)d_in[2];
    const int*   lens  = (const int*)d_in[3];
    float* out = (float*)d_out;

    crf_kernel<<<Bn / 2, NT>>>(inp, trans, tags, lens, out);
}

// round 11
// speedup vs baseline: 1.0837x; 1.0837x over previous
#include <cuda_runtime.h>
#include <cstring>

#define Bn 512
#define Tn 512
#define Nn 64
#define WPB 8            // warps per block, each warp = one batch
#define NT (32 * WPB)

typedef unsigned long long ull;

__device__ __forceinline__ ull fma2(ull a, ull b, ull c) {
    ull d;
    asm("fma.rn.f32x2 %0, %1, %2, %3;" : "=l"(d) : "l"(a), "l"(b), "l"(c));
    return d;
}

__device__ __forceinline__ ull add2(ull a, ull b) {
    ull d;
    asm("add.rn.f32x2 %0, %1, %2;" : "=l"(d) : "l"(a), "l"(b));
    return d;
}

__device__ __forceinline__ ull pack2(float x, float y) {
    float2 f; f.x = x; f.y = y;
    ull u;
    memcpy(&u, &f, 8);
    return u;
}

__global__ void __launch_bounds__(NT) crf_kernel(
    const float* __restrict__ inp,    // [B,T,N]
    const float* __restrict__ trans,  // [N,N]
    const int*   __restrict__ tags,   // [B,T]
    const int*   __restrict__ lens,   // [B]
    float*       __restrict__ out)    // [512 + 4096]
{
    const int w = threadIdx.x >> 5;           // warp in block = batch slot
    const int l = threadIdx.x & 31;
    const int b = blockIdx.x * WPB + w;       // batch

    // fused transition_params copy: 64 elements per block (64*64 = 4096)
    if (threadIdx.x < 64) {
        int idx = blockIdx.x * 64 + threadIdx.x;
        out[Bn + idx] = trans[idx];
    }

    const int cA = 2 * l;
    const int cB = 2 * l + 1;

    // per-warp private double buffer: no inter-warp sync ever needed
    __shared__ float pbuf[WPB][2][Nn];

    const int L    = lens[b];
    const int last = (L - 1) > 0 ? (L - 1) : 0;
    const long baseBT = (long)b * Tn;
    const float* __restrict__ erow = inp + baseBT * Nn;

    // ---------------- sequence score (parallel over t, warp reduce) ----------
    float s = 0.f;
    for (int t = l; t < Tn; t += 32) {
        if (t < L) {
            int tg = tags[baseBT + t];
            s += erow[t * Nn + tg];
            if (t >= 1) {
                int tp = tags[baseBT + t - 1];
                s += trans[tp * Nn + tg];
            }
        }
    }
    #pragma unroll
    for (int o = 16; o > 0; o >>= 1)
        s += __shfl_down_sync(0xffffffffu, s, o);
    const float seqscore = s;   // valid in lane 0

    // ---------------- E columns for cA, cB, packed over i-pairs --------------
    ull EA[32], EB[32];
    #pragma unroll
    for (int i = 0; i < 32; i++) {
        float a0 = __expf(trans[(2 * i)     * Nn + cA]);
        float a1 = __expf(trans[(2 * i + 1) * Nn + cA]);
        float b0 = __expf(trans[(2 * i)     * Nn + cB]);
        float b1 = __expf(trans[(2 * i + 1) * Nn + cB]);
        EA[i] = pack2(a0, a1);
        EB[i] = pack2(b0, b1);
    }

    // ---------------- forward recursion: smem broadcast, syncwarp only -------
    float q0 = __expf(erow[cA]);
    float q1 = __expf(erow[cB]);
    *reinterpret_cast<float2*>(&pbuf[w][0][cA]) = make_float2(q0, q1);
    int K = 0;
    int buf = 0;

#define STEP(XA, XB)                                                         \
    do {                                                                     \
        __syncwarp();                                                        \
        const float4* p4 = reinterpret_cast<const float4*>(pbuf[w][buf]);    \
        ull aA0, aA1, aB0, aB1;                                              \
        float4 v0 = p4[0];                                                   \
        int eb = (__float_as_int(v0.x) >> 23) & 0xFF;                        \
        eb = eb < 64 ? 64 : (eb > 190 ? 190 : eb);                           \
        const float sc = __int_as_float((254 - eb) << 23);                   \
        K += eb - 127;                                                       \
        {                                                                    \
            ull plo = pack2(v0.x, v0.y);                                     \
            ull phi = pack2(v0.z, v0.w);                                     \
            aA0 = fma2(plo, EA[0], 0ull);                                    \
            aA1 = fma2(phi, EA[1], 0ull);                                    \
            aB0 = fma2(plo, EB[0], 0ull);                                    \
            aB1 = fma2(phi, EB[1], 0ull);                                    \
        }                                                                    \
        _Pragma("unroll")                                                    \
        for (int m = 1; m < 16; m++) {                                       \
            float4 v = p4[m];                                                \
            ull plo = pack2(v.x, v.y);                                       \
            ull phi = pack2(v.z, v.w);                                       \
            aA0 = fma2(plo, EA[2 * m],     aA0);                             \
            aA1 = fma2(phi, EA[2 * m + 1], aA1);                             \
            aB0 = fma2(plo, EB[2 * m],     aB0);                             \
            aB1 = fma2(phi, EB[2 * m + 1], aB1);                             \
        }                                                                    \
        ull sA = add2(aA0, aA1);                                             \
        ull sB = add2(aB0, aB1);                                             \
        float2 fA, fB;                                                       \
        memcpy(&fA, &sA, 8);                                                 \
        memcpy(&fB, &sB, 8);                                                 \
        q0 = (XA) * (fA.x + fA.y) * sc;                                      \
        q1 = (XB) * (fB.x + fB.y) * sc;                                      \
        *reinterpret_cast<float2*>(&pbuf[w][buf ^ 1][cA]) =                  \
            make_float2(q0, q1);                                             \
        buf ^= 1;                                                            \
    } while (0)

#define EMLOAD(ROW)                                                          \
    (*reinterpret_cast<const float2*>(                                       \
        erow + ((((ROW) < Tn - 1) ? (ROW) : (Tn - 1)) * Nn) + cA))

    float2 c0 = EMLOAD(1), c1 = EMLOAD(2), c2 = EMLOAD(3), c3 = EMLOAD(4);

    int t = 1;
    for (; t + 3 <= last; t += 4) {
        float2 n0 = EMLOAD(t + 4);
        float2 n1 = EMLOAD(t + 5);
        float2 n2 = EMLOAD(t + 6);
        float2 n3 = EMLOAD(t + 7);
        float x0a = __expf(c0.x), x0b = __expf(c0.y);
        float x1a = __expf(c1.x), x1b = __expf(c1.y);
        float x2a = __expf(c2.x), x2b = __expf(c2.y);
        float x3a = __expf(c3.x), x3b = __expf(c3.y);
        STEP(x0a, x0b);
        STEP(x1a, x1b);
        STEP(x2a, x2b);
        STEP(x3a, x3b);
        c0 = n0; c1 = n1; c2 = n2; c3 = n3;
    }
    if (t <= last) { float xa = __expf(c0.x), xb = __expf(c0.y); STEP(xa, xb); t++; }
    if (t <= last) { float xa = __expf(c1.x), xb = __expf(c1.y); STEP(xa, xb); t++; }
    if (t <= last) { float xa = __expf(c2.x), xb = __expf(c2.y); STEP(xa, xb); t++; }

#undef STEP
#undef EMLOAD

    // ---------------- final log-normalizer (warp reduce) ----------------
    float ssum = q0 + q1;
    #pragma unroll
    for (int o = 16; o > 0; o >>= 1)
        ssum += __shfl_down_sync(0xffffffffu, ssum, o);

    if (l == 0) {
        const float LN2_HI = 0.693145751953125f;
        const float LN2_LO = 1.428606765330187e-06f;
        const float Kf = (float)K;
        const float lognorm = fmaf(Kf, LN2_LO, fmaf(Kf, LN2_HI, __logf(ssum)));
        out[b] = seqscore - lognorm;
    }
}

extern "C" void kernel_launch(void* const* d_in, const int* in_sizes, int n_in,
                              void* d_out, int out_size) {
    const float* inp   = (const float*)d_in[0];
    const float* trans = (const float*)d_in[1];
    const int*   tags  = (const int*)d_in[2];
    const int*   lens  = (const int*)d_in[3];
    float* out = (float*)d_out;

    crf_kernel<<<Bn / WPB, NT>>>(inp, trans, tags, lens, out);
}